// round 15
// baseline (speedup 1.0000x reference)
#include <cuda_runtime.h>
#include <cuda_fp16.h>
#include <cstdint>

#define TEXD   1024
#define TEXP   1025
#define OUTC   16
#define INC    32

// ---- conv GEMM geometry (fp16 m16n8k16, k = channel, row-pair) ----
#define XT        128          // pixels per x-strip (4 warps x 32 px)
#define XSTRIPS   9
#define YSPLIT    29
#define ROWS_PER  36           // 29*36 = 1044 >= 1025
#define SROWS     132          // staged x positions per plane
#define XSTRIDE   48           // bytes per x position (32 B data + 16 pad)
#define CGS       6336         // 132 * 48 : bytes per channel-group
#define PLANE_B   12672        // 2 channel-groups
#define NPLANES   7
#define PL_OFF    16384        // B fragments occupy [0, 16384)
#define SMEM_CONV (PL_OFF + NPLANES * PLANE_B)   // 105088 B -> 2 CTAs/SM
#define NTASK     264          // 2 cg * 132 x per plane
#define NKS       3            // ceil(264/128)
#define CTHREADS  128
#define SLOT(Y)   (((Y) + 7) % 7)

__device__ unsigned short g_filtB[8192];      // prepacked fp16 B fragments
__device__ __half g_tex[TEXP * TEXP * OUTC];  // [y][x][o] channel-last fp16

// ------------------------------ helpers -----------------------------------
__device__ __forceinline__ uint32_t smem_u32(const void* p) {
    uint32_t a;
    asm("{ .reg .u64 t; cvta.to.shared.u64 t, %1; cvt.u32.u64 %0, t; }" : "=r"(a) : "l"(p));
    return a;
}

#define MMA16(C, A0, A1, A2, A3, B0, B1)                                      \
    asm volatile("mma.sync.aligned.m16n8k16.row.col.f32.f16.f16.f32 "         \
                 "{%0,%1,%2,%3}, {%4,%5,%6,%7}, {%8,%9}, {%0,%1,%2,%3};"      \
                 : "+f"((C)[0]), "+f"((C)[1]), "+f"((C)[2]), "+f"((C)[3])     \
                 : "r"(A0), "r"(A1), "r"(A2), "r"(A3), "r"(B0), "r"(B1))

#define LDS32(dst, addr) \
    asm("ld.shared.b32 %0, [%1];" : "=r"(dst) : "r"(addr))

// ---------------------------------------------------------------------------
// Kernel 1: fused MLP (layers 1-2 recomputed per block) + layer-3 warp-per-
// output -> prepacked fp16 B fragments (mapping verified rounds 8-14).
// 256 threads: tid<128 layer1, tid<64 layer2, 8 warps for 8 outputs.
// ---------------------------------------------------------------------------
__global__ void filt_kernel(const float* __restrict__ expr,
                            const float* __restrict__ W1, const float* __restrict__ b1,
                            const float* __restrict__ W2, const float* __restrict__ b2,
                            const float* __restrict__ W3, const float* __restrict__ b3)
{
    __shared__ float sx[76];
    __shared__ float h1[128];
    __shared__ float h2[64];
    const int tid  = threadIdx.x;
    const int lane = tid & 31;
    const int warp = tid >> 5;

    if (tid < 76) sx[tid] = expr[tid];
    __syncthreads();
    if (tid < 128) {
        float a = b1[tid];
        const float* w = W1 + tid * 76;
        #pragma unroll 4
        for (int k = 0; k < 76; ++k) a = fmaf(w[k], sx[k], a);
        h1[tid] = (a >= 0.f) ? a : 0.02f * a;
    }
    __syncthreads();
    if (tid < 64) {
        float a = b2[tid];
        const float* w = W2 + tid * 128;
        #pragma unroll 4
        for (int k = 0; k < 128; ++k) a = fmaf(w[k], h1[k], a);
        h2[tid] = (a >= 0.f) ? a : 0.02f * a;
    }
    __syncthreads();

    const int m = blockIdx.x * 8 + warp;
    const float* w = W3 + m * 64;
    float v = w[lane] * h2[lane] + w[lane + 32] * h2[lane + 32];
    #pragma unroll
    for (int s = 16; s > 0; s >>= 1) v += __shfl_xor_sync(0xFFFFFFFFu, v, s);

    if (lane == 0) {
        float a = tanhf(v + b3[m]);
        int o  = m >> 9;
        int r  = m & 511;
        int c  = r >> 4;
        int t  = r & 15;              // ky*4 + kx
        int j  = (t << 1) | (c >> 4);
        int ck = c & 15;
        int tg = (ck >> 1) & 3;
        int cmp = ((ck >> 3) & 1) | ((o >> 3) << 1);
        int ln  = ((o & 7) << 2) | tg;
        int idx = ((((j * 32 + ln) << 2) | cmp) << 1) | (ck & 1);
        g_filtB[idx] = __half_as_ushort(__float2half_rn(a));
    }
}

// ---------------------------------------------------------------------------
// staging: one data row Y -> fp16 plane (thread stride = 128)
// ---------------------------------------------------------------------------
__device__ __forceinline__ void stage_load(const float* __restrict__ data,
                                           int x0, int Y, int tid,
                                           uint32_t st[NKS][8])
{
    const bool yok = (unsigned)Y < 1024u;
    #pragma unroll
    for (int k = 0; k < NKS; ++k) {
        int t = tid + CTHREADS * k;
        bool ok = (t < NTASK) && yok;
        int cg = (t >= SROWS) ? 1 : 0;
        int s  = t - SROWS * cg;
        int gx = x0 - 2 + s;
        bool xok = ok && ((unsigned)gx < 1024u);
        float v[16];
        #pragma unroll
        for (int i = 0; i < 16; ++i) {
            const float* p = data + (((size_t)(cg * 16 + i)) << 20)
                                  + (((size_t)(Y & 1023)) << 10) + (gx & 1023);
            v[i] = xok ? __ldg(p) : 0.f;
        }
        #pragma unroll
        for (int i = 0; i < 8; ++i) {
            __half2 h = __floats2half2_rn(v[2 * i], v[2 * i + 1]);
            st[k][i] = *(uint32_t*)&h;
        }
    }
}

__device__ __forceinline__ void stage_store(char* plane, int tid,
                                            const uint32_t st[NKS][8])
{
    #pragma unroll
    for (int k = 0; k < NKS; ++k) {
        int t = tid + CTHREADS * k;
        if (t < NTASK) {
            int cg = (t >= SROWS) ? 1 : 0;
            int s  = t - SROWS * cg;
            char* p = plane + cg * CGS + s * XSTRIDE;
            *(uint4*)p        = make_uint4(st[k][0], st[k][1], st[k][2], st[k][3]);
            *(uint4*)(p + 16) = make_uint4(st[k][4], st[k][5], st[k][6], st[k][7]);
        }
    }
}

// ---------------------------------------------------------------------------
// Kernel 2: fp16 m16n8k16 implicit-GEMM conv, row-pair, 2 CTAs/SM.
// 128 threads (4 warps x 32 px = 128 px strip). Ring of 7 planes.
// Pair (y,y+1): A from plane p serves tap p of row y and p-1 of row y+1.
// ---------------------------------------------------------------------------
__global__ void __launch_bounds__(CTHREADS, 2)
conv_kernel(const float* __restrict__ data)
{
    extern __shared__ char smem[];
    const uint32_t sbase = smem_u32(smem);
    const int tid  = threadIdx.x;
    const int warp = tid >> 5;
    const int lane = tid & 31;

    const int x0 = blockIdx.x * XT;
    const int y0 = blockIdx.y * ROWS_PER;
    const int y1 = min(y0 + ROWS_PER - 1, TEXP - 1);

    // B fragments -> smem (16 KB)
    {
        const uint4* src = (const uint4*)g_filtB;
        uint4* dst = (uint4*)smem;
        #pragma unroll
        for (int i = tid; i < 1024; i += CTHREADS) dst[i] = src[i];
    }

    // prologue: stage planes for data rows y0-2 .. y0+2 (5 planes)
    {
        uint32_t st[NKS][8];
        for (int pp = 0; pp < 5; ++pp) {
            int Y = y0 - 2 + pp;
            stage_load(data, x0, Y, tid, st);
            stage_store(smem + PL_OFF + SLOT(Y) * PLANE_B, tid, st);
        }
    }
    __syncthreads();

    const int tg = lane & 3;
    const int g  = lane >> 2;
    const uint32_t tconst = (uint32_t)((warp * 32 + g) * XSTRIDE + 4 * tg);
    const uint32_t bln    = sbase + (uint32_t)(lane << 4);

    for (int y = y0; y <= y1; y += 2) {
        // issue staged loads for data rows y+3, y+4 (hidden behind MMA)
        uint32_t stA[NKS][8], stB[NKS][8];
        stage_load(data, x0, y + 3, tid, stA);
        stage_load(data, x0, y + 4, tid, stB);

        uint32_t pb[5];
        #pragma unroll
        for (int p = 0; p < 5; ++p)
            pb[p] = sbase + PL_OFF + (uint32_t)(SLOT(y - 2 + p) * PLANE_B) + tconst;

        float accY[16], accZ[16];
        #pragma unroll
        for (int i = 0; i < 16; ++i) { accY[i] = 0.f; accZ[i] = 0.f; }

        #pragma unroll
        for (int p = 0; p < 5; ++p) {
            #pragma unroll
            for (int kx = 0; kx < 4; ++kx) {
                #pragma unroll
                for (int cg = 0; cg < 2; ++cg) {
                    const uint32_t ad = pb[p] + (uint32_t)(kx * XSTRIDE + cg * CGS);
                    uint32_t a0, a1, a2, a3, a4, a5, a6, a7;
                    LDS32(a0, ad);          LDS32(a2, ad + 16);
                    LDS32(a1, ad + 384);    LDS32(a3, ad + 400);
                    LDS32(a4, ad + 768);    LDS32(a6, ad + 784);
                    LDS32(a5, ad + 1152);   LDS32(a7, ad + 1168);

                    if (p < 4) {   // row y, tap ky = p
                        uint32_t b0, b1, b2, b3;
                        uint32_t bp = bln + (uint32_t)(((((p * 4 + kx) << 1) | cg)) * 512);
                        asm("ld.shared.v4.b32 {%0,%1,%2,%3}, [%4];"
                            : "=r"(b0), "=r"(b1), "=r"(b2), "=r"(b3) : "r"(bp));
                        MMA16(accY + 0,  a0, a1, a2, a3, b0, b1);
                        MMA16(accY + 4,  a0, a1, a2, a3, b2, b3);
                        MMA16(accY + 8,  a4, a5, a6, a7, b0, b1);
                        MMA16(accY + 12, a4, a5, a6, a7, b2, b3);
                    }
                    if (p > 0) {   // row y+1, tap ky = p-1
                        uint32_t b0, b1, b2, b3;
                        uint32_t bp = bln + (uint32_t)((((((p - 1) * 4 + kx) << 1) | cg)) * 512);
                        asm("ld.shared.v4.b32 {%0,%1,%2,%3}, [%4];"
                            : "=r"(b0), "=r"(b1), "=r"(b2), "=r"(b3) : "r"(bp));
                        MMA16(accZ + 0,  a0, a1, a2, a3, b0, b1);
                        MMA16(accZ + 4,  a0, a1, a2, a3, b2, b3);
                        MMA16(accZ + 8,  a4, a5, a6, a7, b0, b1);
                        MMA16(accZ + 12, a4, a5, a6, a7, b2, b3);
                    }
                }
            }
        }

        // epilogue (fp16 channel-last): thread = pixels xb+{0,8,16,24},
        // channels {2tg,2tg+1} and {2tg+8,2tg+9}
        {
            const int xb = x0 + warp * 32 + g;
            #pragma unroll
            for (int row = 0; row < 2; ++row) {
                const int yy = y + row;
                if (yy <= y1) {
                    const float* acc = row ? accZ : accY;
                    const size_t rowb = (size_t)yy * TEXP;
                    #pragma unroll
                    for (int pi = 0; pi < 4; ++pi) {
                        int x = xb + pi * 8;
                        if (x < TEXP) {
                            const float* A = (pi < 2) ? acc : acc + 8;
                            const float* B = (pi < 2) ? acc + 4 : acc + 12;
                            int o2 = (pi & 1) << 1;
                            __half* dst = g_tex + (rowb + x) * OUTC + 2 * tg;
                            *(__half2*)dst       = __floats2half2_rn(A[o2], A[o2 + 1]);
                            *(__half2*)(dst + 8) = __floats2half2_rn(B[o2], B[o2 + 1]);
                        }
                    }
                }
            }
        }

        // commit planes y+3, y+4 (slots y-4,y-3 mod 7 -> disjoint from reads)
        stage_store(smem + PL_OFF + SLOT(y + 3) * PLANE_B, tid, stA);
        stage_store(smem + PL_OFF + SLOT(y + 4) * PLANE_B, tid, stB);
        __syncthreads();
    }
}

// ---------------------------------------------------------------------------
// Kernel 3: bilinear grid sample from fp16 texture (border, align=False)
// ---------------------------------------------------------------------------
__global__ void sample_kernel(const float* __restrict__ uv, float* __restrict__ out)
{
    int p = blockIdx.x * blockDim.x + threadIdx.x;
    if (p >= TEXD * TEXD) return;

    float x = uv[p];
    float y = uv[(TEXD * TEXD) + p];

    float ix = ((x + 1.f) * (float)TEXP - 1.f) * 0.5f;
    float iy = ((y + 1.f) * (float)TEXP - 1.f) * 0.5f;
    ix = fminf(fmaxf(ix, 0.f), (float)(TEXP - 1));
    iy = fminf(fmaxf(iy, 0.f), (float)(TEXP - 1));

    float fx0 = floorf(ix), fy0 = floorf(iy);
    float wx = ix - fx0, wy = iy - fy0;
    int xi0 = (int)fx0, yi0 = (int)fy0;
    int xi1 = min(xi0 + 1, TEXP - 1);
    int yi1 = min(yi0 + 1, TEXP - 1);

    const uint4* t00 = (const uint4*)&g_tex[(yi0 * TEXP + xi0) * OUTC];
    const uint4* t01 = (const uint4*)&g_tex[(yi0 * TEXP + xi1) * OUTC];
    const uint4* t10 = (const uint4*)&g_tex[(yi1 * TEXP + xi0) * OUTC];
    const uint4* t11 = (const uint4*)&g_tex[(yi1 * TEXP + xi1) * OUTC];

    float w00 = (1.f - wx) * (1.f - wy);
    float w01 = wx * (1.f - wy);
    float w10 = (1.f - wx) * wy;
    float w11 = wx * wy;

    float acc[16];
    #pragma unroll
    for (int i = 0; i < 16; ++i) acc[i] = 0.f;

    #pragma unroll
    for (int h = 0; h < 2; ++h) {      // two uint4 halves (8 channels each)
        uint4 c00 = t00[h], c01 = t01[h], c10 = t10[h], c11 = t11[h];
        const __half2* h00 = (const __half2*)&c00;
        const __half2* h01 = (const __half2*)&c01;
        const __half2* h10 = (const __half2*)&c10;
        const __half2* h11 = (const __half2*)&c11;
        #pragma unroll
        for (int j = 0; j < 4; ++j) {
            float2 f00 = __half22float2(h00[j]);
            float2 f01 = __half22float2(h01[j]);
            float2 f10 = __half22float2(h10[j]);
            float2 f11 = __half22float2(h11[j]);
            int v = h * 8 + j * 2;
            acc[v]     = f00.x * w00 + f01.x * w01 + f10.x * w10 + f11.x * w11;
            acc[v + 1] = f00.y * w00 + f01.y * w01 + f10.y * w10 + f11.y * w11;
        }
    }

    #pragma unroll
    for (int v = 0; v < 16; ++v)
        out[v * (TEXD * TEXD) + p] = acc[v];
}

// ---------------------------------------------------------------------------
extern "C" void kernel_launch(void* const* d_in, const int* in_sizes, int n_in,
                              void* d_out, int out_size)
{
    const float* expr = (const float*)d_in[0];
    const float* uv   = (const float*)d_in[2];
    const float* data = (const float*)d_in[3];
    const float* W1   = (const float*)d_in[4];
    const float* b1   = (const float*)d_in[5];
    const float* W2   = (const float*)d_in[6];
    const float* b2   = (const float*)d_in[7];
    const float* W3   = (const float*)d_in[8];
    const float* b3   = (const float*)d_in[9];
    float* out = (float*)d_out;

    cudaFuncSetAttribute(conv_kernel, cudaFuncAttributeMaxDynamicSharedMemorySize,
                         SMEM_CONV);

    filt_kernel<<<1024, 256>>>(expr, W1, b1, W2, b2, W3, b3);

    dim3 cgrid(XSTRIPS, YSPLIT);
    conv_kernel<<<cgrid, CTHREADS, SMEM_CONV>>>(data);

    sample_kernel<<<(TEXD * TEXD + 255) / 256, 256>>>(uv, out);
}

// round 16
// speedup vs baseline: 1.9230x; 1.9230x over previous
#include <cuda_runtime.h>
#include <cuda_fp16.h>
#include <cstdint>

#define TEXD   1024
#define TEXP   1025
#define OUTC   16
#define INC    32

// ---- conv GEMM geometry (fp16 m16n8k16, k = channel, row-pair) ----
#define XT        256          // pixels per x-strip (8 warps x 32 px)
#define XSTRIPS   5
#define YSPLIT    29
#define ROWS_PER  36           // 29*36 = 1044 >= 1025
#define SROWS     260          // staged x positions per plane
#define XSTRIDE   48           // bytes per x position (32 B data + 16 pad)
#define CGS       12480        // 260 * 48 : bytes per channel-group
#define PLANE_B   24960        // 2 channel-groups
#define NPLANES   7
#define PL_OFF    16384        // B fragments occupy [0, 16384)
#define SMEM_CONV (PL_OFF + NPLANES * PLANE_B)   // 191104 B
#define NTASK     520          // 2 cg * 260 x per plane
#define NKS       3
#define CTHREADS  256
#define SLOT(Y)   (((Y) + 7) % 7)

__device__ unsigned short g_filtB[8192];      // prepacked fp16 B fragments
__device__ float  g_h2[64];
__device__ __half g_tex[TEXP * TEXP * OUTC];  // [y][x][o] channel-last fp16

// ------------------------------ helpers -----------------------------------
__device__ __forceinline__ uint32_t smem_u32(const void* p) {
    uint32_t a;
    asm("{ .reg .u64 t; cvta.to.shared.u64 t, %1; cvt.u32.u64 %0, t; }" : "=r"(a) : "l"(p));
    return a;
}

#define MMA16(C, A0, A1, A2, A3, B0, B1)                                      \
    asm volatile("mma.sync.aligned.m16n8k16.row.col.f32.f16.f16.f32 "         \
                 "{%0,%1,%2,%3}, {%4,%5,%6,%7}, {%8,%9}, {%0,%1,%2,%3};"      \
                 : "+f"((C)[0]), "+f"((C)[1]), "+f"((C)[2]), "+f"((C)[3])     \
                 : "r"(A0), "r"(A1), "r"(A2), "r"(A3), "r"(B0), "r"(B1))

#define LDS32(dst, addr) \
    asm("ld.shared.b32 %0, [%1];" : "=r"(dst) : "r"(addr))

// ---------------------------------------------------------------------------
// Kernel 1a: MLP layers 1-2 (single block, tiny)
// ---------------------------------------------------------------------------
__global__ void mlp12_kernel(const float* __restrict__ expr,
                             const float* __restrict__ W1, const float* __restrict__ b1,
                             const float* __restrict__ W2, const float* __restrict__ b2)
{
    __shared__ float sx[76];
    __shared__ float h1[128];
    const int tid = threadIdx.x;

    if (tid < 76) sx[tid] = expr[tid];
    __syncthreads();
    if (tid < 128) {
        float a = b1[tid];
        const float* w = W1 + tid * 76;
        #pragma unroll 4
        for (int k = 0; k < 76; ++k) a = fmaf(w[k], sx[k], a);
        h1[tid] = (a >= 0.f) ? a : 0.02f * a;
    }
    __syncthreads();
    if (tid < 64) {
        float a = b2[tid];
        const float* w = W2 + tid * 128;
        #pragma unroll 4
        for (int k = 0; k < 128; ++k) a = fmaf(w[k], h1[k], a);
        g_h2[tid] = (a >= 0.f) ? a : 0.02f * a;
    }
}

// ---------------------------------------------------------------------------
// Kernel 1b: MLP layer 3, warp per output -> fp16 B fragments
// (mapping verified rounds 8-14)
// ---------------------------------------------------------------------------
__global__ void filt_kernel(const float* __restrict__ W3, const float* __restrict__ b3)
{
    const int lane = threadIdx.x & 31;
    const int warp = threadIdx.x >> 5;
    const int m    = blockIdx.x * 8 + warp;

    const float* w = W3 + m * 64;
    float v = w[lane] * g_h2[lane] + w[lane + 32] * g_h2[lane + 32];
    #pragma unroll
    for (int s = 16; s > 0; s >>= 1) v += __shfl_xor_sync(0xFFFFFFFFu, v, s);

    if (lane == 0) {
        float a = tanhf(v + b3[m]);
        int o  = m >> 9;
        int r  = m & 511;
        int c  = r >> 4;
        int t  = r & 15;              // ky*4 + kx
        int j  = (t << 1) | (c >> 4);
        int ck = c & 15;
        int tg = (ck >> 1) & 3;
        int cmp = ((ck >> 3) & 1) | ((o >> 3) << 1);
        int ln  = ((o & 7) << 2) | tg;
        int idx = ((((j * 32 + ln) << 2) | cmp) << 1) | (ck & 1);
        g_filtB[idx] = __half_as_ushort(__float2half_rn(a));
    }
}

// ---------------------------------------------------------------------------
// staging (verified rounds 8-14): one data row Y -> fp16 plane.
// ---------------------------------------------------------------------------
__device__ __forceinline__ void stage_load(const float* __restrict__ data,
                                           int x0, int Y, int tid,
                                           uint32_t st[NKS][8])
{
    const bool yok = (unsigned)Y < 1024u;
    #pragma unroll
    for (int k = 0; k < NKS; ++k) {
        int t = tid + CTHREADS * k;
        bool ok = (t < NTASK) && yok;
        int cg = (t >= SROWS) ? 1 : 0;
        int s  = t - SROWS * cg;
        int gx = x0 - 2 + s;
        bool xok = ok && ((unsigned)gx < 1024u);
        float v[16];
        #pragma unroll
        for (int i = 0; i < 16; ++i) {
            const float* p = data + (((size_t)(cg * 16 + i)) << 20)
                                  + (((size_t)(Y & 1023)) << 10) + (gx & 1023);
            v[i] = xok ? __ldg(p) : 0.f;
        }
        #pragma unroll
        for (int i = 0; i < 8; ++i) {
            __half2 h = __floats2half2_rn(v[2 * i], v[2 * i + 1]);
            st[k][i] = *(uint32_t*)&h;
        }
    }
}

__device__ __forceinline__ void stage_store(char* plane, int tid,
                                            const uint32_t st[NKS][8])
{
    #pragma unroll
    for (int k = 0; k < NKS; ++k) {
        int t = tid + CTHREADS * k;
        if (t < NTASK) {
            int cg = (t >= SROWS) ? 1 : 0;
            int s  = t - SROWS * cg;
            char* p = plane + cg * CGS + s * XSTRIDE;
            *(uint4*)p        = make_uint4(st[k][0], st[k][1], st[k][2], st[k][3]);
            *(uint4*)(p + 16) = make_uint4(st[k][4], st[k][5], st[k][6], st[k][7]);
        }
    }
}

// ---------------------------------------------------------------------------
// Kernel 2: fp16 m16n8k16 implicit-GEMM conv, row-pair + B register reuse.
// B fragments loaded at plane p for row y (taps p*4+kx) are held in regs and
// reused at plane p+1 for row y+1 (taps (p+1-1)*4+kx = same) -> B LDS halved.
// ---------------------------------------------------------------------------
__global__ void __launch_bounds__(CTHREADS, 1)
conv_kernel(const float* __restrict__ data)
{
    extern __shared__ char smem[];
    const uint32_t sbase = smem_u32(smem);
    const int tid  = threadIdx.x;
    const int warp = tid >> 5;
    const int lane = tid & 31;

    const int x0 = blockIdx.x * XT;
    const int y0 = blockIdx.y * ROWS_PER;
    const int y1 = min(y0 + ROWS_PER - 1, TEXP - 1);

    // B fragments -> smem (16 KB)
    {
        const uint4* src = (const uint4*)g_filtB;
        uint4* dst = (uint4*)smem;
        #pragma unroll
        for (int i = tid; i < 1024; i += CTHREADS) dst[i] = src[i];
    }

    // prologue: stage planes for data rows y0-2 .. y0+2 (5 planes)
    {
        uint32_t st[NKS][8];
        for (int pp = 0; pp < 5; ++pp) {
            int Y = y0 - 2 + pp;
            stage_load(data, x0, Y, tid, st);
            stage_store(smem + PL_OFF + SLOT(Y) * PLANE_B, tid, st);
        }
    }
    __syncthreads();

    const int tg = lane & 3;
    const int g  = lane >> 2;
    const uint32_t tconst = (uint32_t)((warp * 32 + g) * XSTRIDE + 4 * tg);
    const uint32_t bln    = sbase + (uint32_t)(lane << 4);

    for (int y = y0; y <= y1; y += 2) {
        // issue staged loads for data rows y+3, y+4 (hidden behind MMA)
        uint32_t stA[NKS][8], stB[NKS][8];
        stage_load(data, x0, y + 3, tid, stA);
        stage_load(data, x0, y + 4, tid, stB);

        uint32_t pb[5];
        #pragma unroll
        for (int p = 0; p < 5; ++p)
            pb[p] = sbase + PL_OFF + (uint32_t)(SLOT(y - 2 + p) * PLANE_B) + tconst;

        float accY[16], accZ[16];
        #pragma unroll
        for (int i = 0; i < 16; ++i) { accY[i] = 0.f; accZ[i] = 0.f; }

        uint32_t Bp[4][2][4];   // B fragments carried from plane p to p+1

        #pragma unroll
        for (int p = 0; p < 5; ++p) {
            #pragma unroll
            for (int kx = 0; kx < 4; ++kx) {
                #pragma unroll
                for (int cg = 0; cg < 2; ++cg) {
                    const uint32_t ad = pb[p] + (uint32_t)(kx * XSTRIDE + cg * CGS);
                    uint32_t a0, a1, a2, a3, a4, a5, a6, a7;
                    LDS32(a0, ad);          LDS32(a2, ad + 16);
                    LDS32(a1, ad + 384);    LDS32(a3, ad + 400);
                    LDS32(a4, ad + 768);    LDS32(a6, ad + 784);
                    LDS32(a5, ad + 1152);   LDS32(a7, ad + 1168);

                    if (p > 0) {   // row y+1, tap ky = p-1: reuse carried B
                        MMA16(accZ + 0,  a0, a1, a2, a3, Bp[kx][cg][0], Bp[kx][cg][1]);
                        MMA16(accZ + 4,  a0, a1, a2, a3, Bp[kx][cg][2], Bp[kx][cg][3]);
                        MMA16(accZ + 8,  a4, a5, a6, a7, Bp[kx][cg][0], Bp[kx][cg][1]);
                        MMA16(accZ + 12, a4, a5, a6, a7, Bp[kx][cg][2], Bp[kx][cg][3]);
                    }
                    if (p < 4) {   // row y, tap ky = p: fresh B, then carry
                        uint32_t b0, b1, b2, b3;
                        uint32_t bpa = bln + (uint32_t)(((((p * 4 + kx) << 1) | cg)) * 512);
                        asm("ld.shared.v4.b32 {%0,%1,%2,%3}, [%4];"
                            : "=r"(b0), "=r"(b1), "=r"(b2), "=r"(b3) : "r"(bpa));
                        MMA16(accY + 0,  a0, a1, a2, a3, b0, b1);
                        MMA16(accY + 4,  a0, a1, a2, a3, b2, b3);
                        MMA16(accY + 8,  a4, a5, a6, a7, b0, b1);
                        MMA16(accY + 12, a4, a5, a6, a7, b2, b3);
                        Bp[kx][cg][0] = b0; Bp[kx][cg][1] = b1;
                        Bp[kx][cg][2] = b2; Bp[kx][cg][3] = b3;
                    }
                }
            }
        }

        // epilogue (fp16 channel-last): thread = pixels xb+{0,8,16,24},
        // channels {2tg,2tg+1} and {2tg+8,2tg+9}
        {
            const int xb = x0 + warp * 32 + g;
            #pragma unroll
            for (int row = 0; row < 2; ++row) {
                const int yy = y + row;
                if (yy <= y1) {
                    const float* acc = row ? accZ : accY;
                    const size_t rowb = (size_t)yy * TEXP;
                    #pragma unroll
                    for (int pi = 0; pi < 4; ++pi) {
                        int x = xb + pi * 8;
                        if (x < TEXP) {
                            const float* A = (pi < 2) ? acc : acc + 8;
                            const float* B = (pi < 2) ? acc + 4 : acc + 12;
                            int o2 = (pi & 1) << 1;
                            __half* dst = g_tex + (rowb + x) * OUTC + 2 * tg;
                            *(__half2*)dst       = __floats2half2_rn(A[o2], A[o2 + 1]);
                            *(__half2*)(dst + 8) = __floats2half2_rn(B[o2], B[o2 + 1]);
                        }
                    }
                }
            }
        }

        // commit planes y+3, y+4 (slots y-4,y-3 mod 7 -> disjoint from reads)
        stage_store(smem + PL_OFF + SLOT(y + 3) * PLANE_B, tid, stA);
        stage_store(smem + PL_OFF + SLOT(y + 4) * PLANE_B, tid, stB);
        __syncthreads();
    }
}

// ---------------------------------------------------------------------------
// Kernel 3: bilinear grid sample from fp16 texture (border, align=False)
// ---------------------------------------------------------------------------
__global__ void sample_kernel(const float* __restrict__ uv, float* __restrict__ out)
{
    int p = blockIdx.x * blockDim.x + threadIdx.x;
    if (p >= TEXD * TEXD) return;

    float x = uv[p];
    float y = uv[(TEXD * TEXD) + p];

    float ix = ((x + 1.f) * (float)TEXP - 1.f) * 0.5f;
    float iy = ((y + 1.f) * (float)TEXP - 1.f) * 0.5f;
    ix = fminf(fmaxf(ix, 0.f), (float)(TEXP - 1));
    iy = fminf(fmaxf(iy, 0.f), (float)(TEXP - 1));

    float fx0 = floorf(ix), fy0 = floorf(iy);
    float wx = ix - fx0, wy = iy - fy0;
    int xi0 = (int)fx0, yi0 = (int)fy0;
    int xi1 = min(xi0 + 1, TEXP - 1);
    int yi1 = min(yi0 + 1, TEXP - 1);

    const uint4* t00 = (const uint4*)&g_tex[(yi0 * TEXP + xi0) * OUTC];
    const uint4* t01 = (const uint4*)&g_tex[(yi0 * TEXP + xi1) * OUTC];
    const uint4* t10 = (const uint4*)&g_tex[(yi1 * TEXP + xi0) * OUTC];
    const uint4* t11 = (const uint4*)&g_tex[(yi1 * TEXP + xi1) * OUTC];

    float w00 = (1.f - wx) * (1.f - wy);
    float w01 = wx * (1.f - wy);
    float w10 = (1.f - wx) * wy;
    float w11 = wx * wy;

    float acc[16];
    #pragma unroll
    for (int i = 0; i < 16; ++i) acc[i] = 0.f;

    #pragma unroll
    for (int h = 0; h < 2; ++h) {      // two uint4 halves (8 channels each)
        uint4 c00 = t00[h], c01 = t01[h], c10 = t10[h], c11 = t11[h];
        const __half2* h00 = (const __half2*)&c00;
        const __half2* h01 = (const __half2*)&c01;
        const __half2* h10 = (const __half2*)&c10;
        const __half2* h11 = (const __half2*)&c11;
        #pragma unroll
        for (int j = 0; j < 4; ++j) {
            float2 f00 = __half22float2(h00[j]);
            float2 f01 = __half22float2(h01[j]);
            float2 f10 = __half22float2(h10[j]);
            float2 f11 = __half22float2(h11[j]);
            int v = h * 8 + j * 2;
            acc[v]     = f00.x * w00 + f01.x * w01 + f10.x * w10 + f11.x * w11;
            acc[v + 1] = f00.y * w00 + f01.y * w01 + f10.y * w10 + f11.y * w11;
        }
    }

    #pragma unroll
    for (int v = 0; v < 16; ++v)
        out[v * (TEXD * TEXD) + p] = acc[v];
}

// ---------------------------------------------------------------------------
extern "C" void kernel_launch(void* const* d_in, const int* in_sizes, int n_in,
                              void* d_out, int out_size)
{
    const float* expr = (const float*)d_in[0];
    const float* uv   = (const float*)d_in[2];
    const float* data = (const float*)d_in[3];
    const float* W1   = (const float*)d_in[4];
    const float* b1   = (const float*)d_in[5];
    const float* W2   = (const float*)d_in[6];
    const float* b2   = (const float*)d_in[7];
    const float* W3   = (const float*)d_in[8];
    const float* b3   = (const float*)d_in[9];
    float* out = (float*)d_out;

    cudaFuncSetAttribute(conv_kernel, cudaFuncAttributeMaxDynamicSharedMemorySize,
                         SMEM_CONV);

    mlp12_kernel<<<1, 128>>>(expr, W1, b1, W2, b2);
    filt_kernel<<<1024, 256>>>(W3, b3);

    dim3 cgrid(XSTRIPS, YSPLIT);
    conv_kernel<<<cgrid, CTHREADS, SMEM_CONV>>>(data);

    sample_kernel<<<(TEXD * TEXD + 255) / 256, 256>>>(uv, out);
}

// round 17
// speedup vs baseline: 1.9722x; 1.0256x over previous
#include <cuda_runtime.h>
#include <cuda_fp16.h>
#include <cstdint>

#define TEXD   1024
#define TEXP   1025
#define OUTC   16
#define INC    32

// ---- conv GEMM geometry (fp16 m16n8k16, k = channel, row-pair) ----
#define XT        256          // pixels per x-strip (8 warps x 32 px)
#define XSTRIPS   5
#define YSPLIT    29
#define ROWS_PER  36           // 29*36 = 1044 >= 1025
#define SROWS     260          // staged x positions per plane
#define XSTRIDE   48           // bytes per x position (32 B data + 16 pad)
#define CGS       12480        // 260 * 48 : bytes per channel-group
#define PLANE_B   24960        // 2 channel-groups
#define NPLANES   7
#define PL_OFF    16384        // B fragments occupy [0, 16384)
#define SMEM_CONV (PL_OFF + NPLANES * PLANE_B)   // 191104 B
#define NTASK     520          // 2 cg * 260 x per plane
#define NKS       3
#define CTHREADS  256
#define SLOT(Y)   (((Y) + 7) % 7)

__device__ unsigned short g_filtB[8192];      // prepacked fp16 B fragments
__device__ float  g_h2[64];
__device__ __half g_tex[TEXP * TEXP * OUTC];  // [y][x][o] channel-last fp16

// ------------------------------ helpers -----------------------------------
__device__ __forceinline__ uint32_t smem_u32(const void* p) {
    uint32_t a;
    asm("{ .reg .u64 t; cvta.to.shared.u64 t, %1; cvt.u32.u64 %0, t; }" : "=r"(a) : "l"(p));
    return a;
}

#define MMA16(C, A0, A1, A2, A3, B0, B1)                                      \
    asm volatile("mma.sync.aligned.m16n8k16.row.col.f32.f16.f16.f32 "         \
                 "{%0,%1,%2,%3}, {%4,%5,%6,%7}, {%8,%9}, {%0,%1,%2,%3};"      \
                 : "+f"((C)[0]), "+f"((C)[1]), "+f"((C)[2]), "+f"((C)[3])     \
                 : "r"(A0), "r"(A1), "r"(A2), "r"(A3), "r"(B0), "r"(B1))

#define LDMX4(R0, R1, R2, R3, addr)                                           \
    asm volatile("ldmatrix.sync.aligned.m8n8.x4.shared.b16 {%0,%1,%2,%3}, [%4];" \
                 : "=r"(R0), "=r"(R1), "=r"(R2), "=r"(R3) : "r"(addr))

// ---------------------------------------------------------------------------
// Kernel 1a: MLP layers 1-2 (single block, tiny)
// ---------------------------------------------------------------------------
__global__ void mlp12_kernel(const float* __restrict__ expr,
                             const float* __restrict__ W1, const float* __restrict__ b1,
                             const float* __restrict__ W2, const float* __restrict__ b2)
{
    __shared__ float sx[76];
    __shared__ float h1[128];
    const int tid = threadIdx.x;

    if (tid < 76) sx[tid] = expr[tid];
    __syncthreads();
    if (tid < 128) {
        float a = b1[tid];
        const float* w = W1 + tid * 76;
        #pragma unroll 4
        for (int k = 0; k < 76; ++k) a = fmaf(w[k], sx[k], a);
        h1[tid] = (a >= 0.f) ? a : 0.02f * a;
    }
    __syncthreads();
    if (tid < 64) {
        float a = b2[tid];
        const float* w = W2 + tid * 128;
        #pragma unroll 4
        for (int k = 0; k < 128; ++k) a = fmaf(w[k], h1[k], a);
        g_h2[tid] = (a >= 0.f) ? a : 0.02f * a;
    }
}

// ---------------------------------------------------------------------------
// Kernel 1b: MLP layer 3, warp per output -> fp16 B fragments
// (mapping verified rounds 8-16)
// ---------------------------------------------------------------------------
__global__ void filt_kernel(const float* __restrict__ W3, const float* __restrict__ b3)
{
    const int lane = threadIdx.x & 31;
    const int warp = threadIdx.x >> 5;
    const int m    = blockIdx.x * 8 + warp;

    const float* w = W3 + m * 64;
    float v = w[lane] * g_h2[lane] + w[lane + 32] * g_h2[lane + 32];
    #pragma unroll
    for (int s = 16; s > 0; s >>= 1) v += __shfl_xor_sync(0xFFFFFFFFu, v, s);

    if (lane == 0) {
        float a = tanhf(v + b3[m]);
        int o  = m >> 9;
        int r  = m & 511;
        int c  = r >> 4;
        int t  = r & 15;              // ky*4 + kx
        int j  = (t << 1) | (c >> 4);
        int ck = c & 15;
        int tg = (ck >> 1) & 3;
        int cmp = ((ck >> 3) & 1) | ((o >> 3) << 1);
        int ln  = ((o & 7) << 2) | tg;
        int idx = ((((j * 32 + ln) << 2) | cmp) << 1) | (ck & 1);
        g_filtB[idx] = __half_as_ushort(__float2half_rn(a));
    }
}

// ---------------------------------------------------------------------------
// staging (verified rounds 8-16): one data row Y -> fp16 plane.
// ---------------------------------------------------------------------------
__device__ __forceinline__ void stage_load(const float* __restrict__ data,
                                           int x0, int Y, int tid,
                                           uint32_t st[NKS][8])
{
    const bool yok = (unsigned)Y < 1024u;
    #pragma unroll
    for (int k = 0; k < NKS; ++k) {
        int t = tid + CTHREADS * k;
        bool ok = (t < NTASK) && yok;
        int cg = (t >= SROWS) ? 1 : 0;
        int s  = t - SROWS * cg;
        int gx = x0 - 2 + s;
        bool xok = ok && ((unsigned)gx < 1024u);
        float v[16];
        #pragma unroll
        for (int i = 0; i < 16; ++i) {
            const float* p = data + (((size_t)(cg * 16 + i)) << 20)
                                  + (((size_t)(Y & 1023)) << 10) + (gx & 1023);
            v[i] = xok ? __ldg(p) : 0.f;
        }
        #pragma unroll
        for (int i = 0; i < 8; ++i) {
            __half2 h = __floats2half2_rn(v[2 * i], v[2 * i + 1]);
            st[k][i] = *(uint32_t*)&h;
        }
    }
}

__device__ __forceinline__ void stage_store(char* plane, int tid,
                                            const uint32_t st[NKS][8])
{
    #pragma unroll
    for (int k = 0; k < NKS; ++k) {
        int t = tid + CTHREADS * k;
        if (t < NTASK) {
            int cg = (t >= SROWS) ? 1 : 0;
            int s  = t - SROWS * cg;
            char* p = plane + cg * CGS + s * XSTRIDE;
            *(uint4*)p        = make_uint4(st[k][0], st[k][1], st[k][2], st[k][3]);
            *(uint4*)(p + 16) = make_uint4(st[k][4], st[k][5], st[k][6], st[k][7]);
        }
    }
}

// ---------------------------------------------------------------------------
// Kernel 2: fp16 m16n8k16 implicit-GEMM conv, row-pair + ldmatrix A loads.
// ldmatrix m8n8.x4 lane address: pixel (w*32 + (lane&15) + kx) stride 48 B,
// byte +16 for k-hi half; matrices [r0..r3] = canonical {a0,a1,a2,a3}.
// Conflict-free: 8 rows at 12-word stride tile all 32 banks.
// ---------------------------------------------------------------------------
__global__ void __launch_bounds__(CTHREADS, 1)
conv_kernel(const float* __restrict__ data)
{
    extern __shared__ char smem[];
    const uint32_t sbase = smem_u32(smem);
    const int tid  = threadIdx.x;
    const int warp = tid >> 5;
    const int lane = tid & 31;

    const int x0 = blockIdx.x * XT;
    const int y0 = blockIdx.y * ROWS_PER;
    const int y1 = min(y0 + ROWS_PER - 1, TEXP - 1);

    // B fragments -> smem (16 KB)
    {
        const uint4* src = (const uint4*)g_filtB;
        uint4* dst = (uint4*)smem;
        #pragma unroll
        for (int i = tid; i < 1024; i += CTHREADS) dst[i] = src[i];
    }

    // prologue: stage planes for data rows y0-2 .. y0+2 (5 planes)
    {
        uint32_t st[NKS][8];
        for (int pp = 0; pp < 5; ++pp) {
            int Y = y0 - 2 + pp;
            stage_load(data, x0, Y, tid, st);
            stage_store(smem + PL_OFF + SLOT(Y) * PLANE_B, tid, st);
        }
    }
    __syncthreads();

    const int tg = lane & 3;
    const int g  = lane >> 2;
    // ldmatrix per-lane base: pixel (w*32 + (lane&15)), k-half byte offset
    const uint32_t aconst = (uint32_t)((warp * 32 + (lane & 15)) * XSTRIDE
                                       + ((lane >> 4) << 4));
    const uint32_t bln    = sbase + (uint32_t)(lane << 4);

    for (int y = y0; y <= y1; y += 2) {
        // issue staged loads for data rows y+3, y+4 (hidden behind MMA)
        uint32_t stA[NKS][8], stB[NKS][8];
        stage_load(data, x0, y + 3, tid, stA);
        stage_load(data, x0, y + 4, tid, stB);

        uint32_t pb[5];
        #pragma unroll
        for (int p = 0; p < 5; ++p)
            pb[p] = sbase + PL_OFF + (uint32_t)(SLOT(y - 2 + p) * PLANE_B) + aconst;

        float accY[16], accZ[16];
        #pragma unroll
        for (int i = 0; i < 16; ++i) { accY[i] = 0.f; accZ[i] = 0.f; }

        #pragma unroll
        for (int p = 0; p < 5; ++p) {
            #pragma unroll
            for (int kx = 0; kx < 4; ++kx) {
                #pragma unroll
                for (int cg = 0; cg < 2; ++cg) {
                    const uint32_t ad = pb[p] + (uint32_t)(kx * XSTRIDE + cg * CGS);
                    uint32_t a0, a1, a2, a3, a4, a5, a6, a7;
                    LDMX4(a0, a1, a2, a3, ad);                       // m-tile 0
                    LDMX4(a4, a5, a6, a7, ad + 16 * XSTRIDE);        // m-tile 1

                    if (p < 4) {   // row y, tap ky = p
                        uint32_t b0, b1, b2, b3;
                        uint32_t bp = bln + (uint32_t)(((((p * 4 + kx) << 1) | cg)) * 512);
                        asm("ld.shared.v4.b32 {%0,%1,%2,%3}, [%4];"
                            : "=r"(b0), "=r"(b1), "=r"(b2), "=r"(b3) : "r"(bp));
                        MMA16(accY + 0,  a0, a1, a2, a3, b0, b1);
                        MMA16(accY + 4,  a0, a1, a2, a3, b2, b3);
                        MMA16(accY + 8,  a4, a5, a6, a7, b0, b1);
                        MMA16(accY + 12, a4, a5, a6, a7, b2, b3);
                    }
                    if (p > 0) {   // row y+1, tap ky = p-1
                        uint32_t b0, b1, b2, b3;
                        uint32_t bp = bln + (uint32_t)((((((p - 1) * 4 + kx) << 1) | cg)) * 512);
                        asm("ld.shared.v4.b32 {%0,%1,%2,%3}, [%4];"
                            : "=r"(b0), "=r"(b1), "=r"(b2), "=r"(b3) : "r"(bp));
                        MMA16(accZ + 0,  a0, a1, a2, a3, b0, b1);
                        MMA16(accZ + 4,  a0, a1, a2, a3, b2, b3);
                        MMA16(accZ + 8,  a4, a5, a6, a7, b0, b1);
                        MMA16(accZ + 12, a4, a5, a6, a7, b2, b3);
                    }
                }
            }
        }

        // epilogue (fp16 channel-last): thread = pixels xb+{0,8,16,24},
        // channels {2tg,2tg+1} and {2tg+8,2tg+9}
        {
            const int xb = x0 + warp * 32 + g;
            #pragma unroll
            for (int row = 0; row < 2; ++row) {
                const int yy = y + row;
                if (yy <= y1) {
                    const float* acc = row ? accZ : accY;
                    const size_t rowb = (size_t)yy * TEXP;
                    #pragma unroll
                    for (int pi = 0; pi < 4; ++pi) {
                        int x = xb + pi * 8;
                        if (x < TEXP) {
                            const float* A = (pi < 2) ? acc : acc + 8;
                            const float* B = (pi < 2) ? acc + 4 : acc + 12;
                            int o2 = (pi & 1) << 1;
                            __half* dst = g_tex + (rowb + x) * OUTC + 2 * tg;
                            *(__half2*)dst       = __floats2half2_rn(A[o2], A[o2 + 1]);
                            *(__half2*)(dst + 8) = __floats2half2_rn(B[o2], B[o2 + 1]);
                        }
                    }
                }
            }
        }

        // commit planes y+3, y+4 (slots y-4,y-3 mod 7 -> disjoint from reads)
        stage_store(smem + PL_OFF + SLOT(y + 3) * PLANE_B, tid, stA);
        stage_store(smem + PL_OFF + SLOT(y + 4) * PLANE_B, tid, stB);
        __syncthreads();
    }
}

// ---------------------------------------------------------------------------
// Kernel 3: bilinear grid sample from fp16 texture (border, align=False)
// ---------------------------------------------------------------------------
__global__ void sample_kernel(const float* __restrict__ uv, float* __restrict__ out)
{
    int p = blockIdx.x * blockDim.x + threadIdx.x;
    if (p >= TEXD * TEXD) return;

    float x = uv[p];
    float y = uv[(TEXD * TEXD) + p];

    float ix = ((x + 1.f) * (float)TEXP - 1.f) * 0.5f;
    float iy = ((y + 1.f) * (float)TEXP - 1.f) * 0.5f;
    ix = fminf(fmaxf(ix, 0.f), (float)(TEXP - 1));
    iy = fminf(fmaxf(iy, 0.f), (float)(TEXP - 1));

    float fx0 = floorf(ix), fy0 = floorf(iy);
    float wx = ix - fx0, wy = iy - fy0;
    int xi0 = (int)fx0, yi0 = (int)fy0;
    int xi1 = min(xi0 + 1, TEXP - 1);
    int yi1 = min(yi0 + 1, TEXP - 1);

    const uint4* t00 = (const uint4*)&g_tex[(yi0 * TEXP + xi0) * OUTC];
    const uint4* t01 = (const uint4*)&g_tex[(yi0 * TEXP + xi1) * OUTC];
    const uint4* t10 = (const uint4*)&g_tex[(yi1 * TEXP + xi0) * OUTC];
    const uint4* t11 = (const uint4*)&g_tex[(yi1 * TEXP + xi1) * OUTC];

    float w00 = (1.f - wx) * (1.f - wy);
    float w01 = wx * (1.f - wy);
    float w10 = (1.f - wx) * wy;
    float w11 = wx * wy;

    float acc[16];
    #pragma unroll
    for (int i = 0; i < 16; ++i) acc[i] = 0.f;

    #pragma unroll
    for (int h = 0; h < 2; ++h) {      // two uint4 halves (8 channels each)
        uint4 c00 = t00[h], c01 = t01[h], c10 = t10[h], c11 = t11[h];
        const __half2* h00 = (const __half2*)&c00;
        const __half2* h01 = (const __half2*)&c01;
        const __half2* h10 = (const __half2*)&c10;
        const __half2* h11 = (const __half2*)&c11;
        #pragma unroll
        for (int j = 0; j < 4; ++j) {
            float2 f00 = __half22float2(h00[j]);
            float2 f01 = __half22float2(h01[j]);
            float2 f10 = __half22float2(h10[j]);
            float2 f11 = __half22float2(h11[j]);
            int v = h * 8 + j * 2;
            acc[v]     = f00.x * w00 + f01.x * w01 + f10.x * w10 + f11.x * w11;
            acc[v + 1] = f00.y * w00 + f01.y * w01 + f10.y * w10 + f11.y * w11;
        }
    }

    #pragma unroll
    for (int v = 0; v < 16; ++v)
        out[v * (TEXD * TEXD) + p] = acc[v];
}

// ---------------------------------------------------------------------------
extern "C" void kernel_launch(void* const* d_in, const int* in_sizes, int n_in,
                              void* d_out, int out_size)
{
    const float* expr = (const float*)d_in[0];
    const float* uv   = (const float*)d_in[2];
    const float* data = (const float*)d_in[3];
    const float* W1   = (const float*)d_in[4];
    const float* b1   = (const float*)d_in[5];
    const float* W2   = (const float*)d_in[6];
    const float* b2   = (const float*)d_in[7];
    const float* W3   = (const float*)d_in[8];
    const float* b3   = (const float*)d_in[9];
    float* out = (float*)d_out;

    cudaFuncSetAttribute(conv_kernel, cudaFuncAttributeMaxDynamicSharedMemorySize,
                         SMEM_CONV);

    mlp12_kernel<<<1, 128>>>(expr, W1, b1, W2, b2);
    filt_kernel<<<1024, 256>>>(W3, b3);

    dim3 cgrid(XSTRIPS, YSPLIT);
    conv_kernel<<<cgrid, CTHREADS, SMEM_CONV>>>(data);

    sample_kernel<<<(TEXD * TEXD + 255) / 256, 256>>>(uv, out);
}